// round 4
// baseline (speedup 1.0000x reference)
#include <cuda_runtime.h>
#include <math.h>

// ---------------------------------------------------------------------------
// Problem constants
// ---------------------------------------------------------------------------
namespace {
constexpr int NB = 2, NS = 1024, NHID = 1024, NHEAD = 8, DHEAD = 128;
constexpr int NEXP = 8, NMI = 1024, NSI = 2048;
constexpr int NT = NB * NS;          // 2048 tokens
constexpr int NSLOT = 2 * NT;        // 4096 expert slots (top-2)

constexpr int BM = 128, BN = 128, BK = 16, PADK = BK + 4;
constexpr int STAGES = 3;
constexpr int SMEM_WORDS_HALF = STAGES * BM * PADK;            // per A or B
constexpr int SMEM_BYTES = 2 * SMEM_WORDS_HALF * (int)sizeof(float);  // 61440
}

// ---------------------------------------------------------------------------
// Static device scratch (no allocations allowed)
// ---------------------------------------------------------------------------
__device__ float d_xn[NT * NHID];
__device__ float d_qt[NT * NHID];
__device__ float d_kt[NT * NHID];
__device__ float d_vt[NT * NHID];
__device__ float d_qr[NT * NHID];     // (B,NH,S,HD) rope'd + scaled
__device__ float d_kr[NT * NHID];     // (B,NH,S,HD)
__device__ float d_vrT[NT * NHID];    // (B,NH,HD,S)
__device__ float d_scores[(long)NB * NHEAD * NS * NS];   // 64 MB
__device__ float d_ctx[NT * NHID];
__device__ float d_x1[NT * NHID];
__device__ float d_xg[NSLOT * NHID];
__device__ float d_gbuf[NSLOT * NMI];
__device__ float d_ubuf[NSLOT * NMI];
__device__ float d_ybuf[NSLOT * NHID];
__device__ float d_gs[NT * NSI];
__device__ float d_us[NT * NSI];
__device__ float d_sh[NT * NHID];
__device__ int   d_cnt[NEXP];
__device__ int   d_off[NEXP];
__device__ int   d_e0[NT], d_e1[NT], d_r0[NT], d_r1[NT], d_s0[NT], d_s1[NT];
__device__ float d_w0[NT], d_w1[NT];

// ---------------------------------------------------------------------------
// TF32 tensor-core GEMM:  C[M,N] = A[M,K] * B^T  with B stored (N,K) row-major
// 128x128x16 block tile, 256 threads = 8 warps, each warp 64x32 (4x4 mma m16n8k8)
// 3-stage cp.async pipeline, ONE __syncthreads per k-iter, dynamic smem.
// M may be ragged (zfill + store guards). N, K multiples of 128 / 16.
// ---------------------------------------------------------------------------
__device__ __forceinline__ unsigned smem_u32(const void* p) {
    return (unsigned)__cvta_generic_to_shared(p);
}

__device__ __forceinline__ void cp16(unsigned dst, const void* src, bool pred) {
    int sz = pred ? 16 : 0;
    asm volatile("cp.async.cg.shared.global [%0], [%1], 16, %2;\n"
                 :: "r"(dst), "l"(src), "r"(sz));
}

__device__ __forceinline__ unsigned f2tf32(float x) {
    unsigned r;
    asm("cvt.rna.tf32.f32 %0, %1;" : "=r"(r) : "f"(x));
    return r;
}

__device__ __forceinline__ void mma_tf32(float c[4],
    unsigned a0, unsigned a1, unsigned a2, unsigned a3,
    unsigned b0, unsigned b1)
{
    asm volatile(
        "mma.sync.aligned.m16n8k8.row.col.f32.tf32.tf32.f32 "
        "{%0,%1,%2,%3}, {%4,%5,%6,%7}, {%8,%9}, {%0,%1,%2,%3};\n"
        : "+f"(c[0]), "+f"(c[1]), "+f"(c[2]), "+f"(c[3])
        : "r"(a0), "r"(a1), "r"(a2), "r"(a3), "r"(b0), "r"(b1));
}

__device__ __forceinline__ void mmgemm_body(
    const float* __restrict__ A, const float* __restrict__ Bm,
    float* __restrict__ C, const float* __restrict__ resid,
    int M, int K, int lda, int ldb, int ldc)
{
    extern __shared__ float sm[];
    float (*As)[BM][PADK] = reinterpret_cast<float (*)[BM][PADK]>(sm);
    float (*Bs)[BM][PADK] =
        reinterpret_cast<float (*)[BM][PADK]>(sm + SMEM_WORDS_HALF);

    const int tid  = threadIdx.x;
    const int wid  = tid >> 5;
    const int lane = tid & 31;
    const int g    = lane >> 2;          // 0..7
    const int tg   = lane & 3;           // 0..3
    const int wm   = (wid & 1) * 64;     // warp m-offset
    const int wn   = (wid >> 1) * 32;    // warp n-offset
    const int row0 = blockIdx.y * BM;
    const int col0 = blockIdx.x * BN;
    if (row0 >= M) return;

    float c[4][4][4];
#pragma unroll
    for (int mi = 0; mi < 4; ++mi)
#pragma unroll
        for (int ni = 0; ni < 4; ++ni)
#pragma unroll
            for (int r = 0; r < 4; ++r) c[mi][ni][r] = 0.f;

    const int lr = tid >> 2;             // 0..63
    const int lq = (tid & 3) * 4;        // 0,4,8,12
    const int niter = K / BK;

    // ---- prologue: stage 0,1 ----
#pragma unroll
    for (int st = 0; st < 2; ++st) {
        if (st < niter) {
            const int k0 = st * BK;
#pragma unroll
            for (int h = 0; h < 2; ++h) {
                int r = lr + h * 64;
                cp16(smem_u32(&As[st][r][lq]),
                     A + (long)(row0 + r) * lda + k0 + lq, (row0 + r) < M);
            }
#pragma unroll
            for (int h = 0; h < 2; ++h) {
                int r = lr + h * 64;
                cp16(smem_u32(&Bs[st][r][lq]),
                     Bm + (long)(col0 + r) * ldb + k0 + lq, true);
            }
        }
        asm volatile("cp.async.commit_group;\n");
    }

    int s = 0;
    for (int it = 0; it < niter; ++it) {
        asm volatile("cp.async.wait_group 1;\n");
        __syncthreads();

        const int pf = it + 2;
        if (pf < niter) {
            int sl = s + 2; if (sl >= STAGES) sl -= STAGES;
            const int k0 = pf * BK;
#pragma unroll
            for (int h = 0; h < 2; ++h) {
                int r = lr + h * 64;
                cp16(smem_u32(&As[sl][r][lq]),
                     A + (long)(row0 + r) * lda + k0 + lq, (row0 + r) < M);
            }
#pragma unroll
            for (int h = 0; h < 2; ++h) {
                int r = lr + h * 64;
                cp16(smem_u32(&Bs[sl][r][lq]),
                     Bm + (long)(col0 + r) * ldb + k0 + lq, true);
            }
        }
        asm volatile("cp.async.commit_group;\n");

#pragma unroll
        for (int kk = 0; kk < 2; ++kk) {
            const int kb = kk * 8;
            unsigned af[4][4], bf[4][2];
#pragma unroll
            for (int mi = 0; mi < 4; ++mi) {
                int mrow = wm + mi * 16;
                af[mi][0] = f2tf32(As[s][mrow + g    ][kb + tg    ]);
                af[mi][1] = f2tf32(As[s][mrow + g + 8][kb + tg    ]);
                af[mi][2] = f2tf32(As[s][mrow + g    ][kb + tg + 4]);
                af[mi][3] = f2tf32(As[s][mrow + g + 8][kb + tg + 4]);
            }
#pragma unroll
            for (int ni = 0; ni < 4; ++ni) {
                int nrow = wn + ni * 8;
                bf[ni][0] = f2tf32(Bs[s][nrow + g][kb + tg    ]);
                bf[ni][1] = f2tf32(Bs[s][nrow + g][kb + tg + 4]);
            }
#pragma unroll
            for (int mi = 0; mi < 4; ++mi)
#pragma unroll
                for (int ni = 0; ni < 4; ++ni)
                    mma_tf32(c[mi][ni], af[mi][0], af[mi][1], af[mi][2], af[mi][3],
                             bf[ni][0], bf[ni][1]);
        }
        if (++s >= STAGES) s = 0;
    }

    // ---- epilogue ----
#pragma unroll
    for (int mi = 0; mi < 4; ++mi) {
#pragma unroll
        for (int half = 0; half < 2; ++half) {
            int r = row0 + wm + mi * 16 + g + half * 8;
            if (r < M) {
#pragma unroll
                for (int ni = 0; ni < 4; ++ni) {
                    long off = (long)r * ldc + col0 + wn + ni * 8 + tg * 2;
                    float2 v;
                    v.x = c[mi][ni][half * 2 + 0];
                    v.y = c[mi][ni][half * 2 + 1];
                    if (resid) {
                        float2 rr = *(const float2*)(resid + off);
                        v.x += rr.x; v.y += rr.y;
                    }
                    *(float2*)(C + off) = v;
                }
            }
        }
    }
}

// ---- generic batched (A * B^T); used for scores (causal), PV, O-proj, shared-down
template <bool CAUSAL>
__global__ __launch_bounds__(256, 2)
void sgemm_bat(
    const float* __restrict__ A, const float* __restrict__ Bm,
    float* __restrict__ C, const float* __restrict__ resid,
    int M, int K, int lda, int ldb, int ldc,
    long sA, long sB, long sC_hi, long sC_lo)
{
    int z = blockIdx.z;
    if (CAUSAL) {
        if (blockIdx.x > blockIdx.y) return;   // tiles strictly above diagonal
    }
    mmgemm_body(A + (long)z * sA, Bm + (long)z * sB,
                C + (long)(z >> 3) * sC_hi + (long)(z & 7) * sC_lo,
                resid, M, K, lda, ldb, ldc);
}

// ---- fused Q/K/V projection: z selects the weight + destination
__global__ __launch_bounds__(256, 2)
void qkv_k(const float* __restrict__ xn,
           const float* __restrict__ qw, const float* __restrict__ kw,
           const float* __restrict__ vw,
           float* __restrict__ qt, float* __restrict__ kt, float* __restrict__ vt)
{
    int z = blockIdx.z;
    const float* B = (z == 0) ? qw : (z == 1) ? kw : vw;
    float* C       = (z == 0) ? qt : (z == 1) ? kt : vt;
    mmgemm_body(xn, B, C, nullptr, NT, NHID, NHID, NHID, NHID);
}

// ---- fused shared-MLP gate+up: z selects sg->gs / su->us
__global__ __launch_bounds__(256, 2)
void shup_k(const float* __restrict__ xn,
            const float* __restrict__ sg, const float* __restrict__ su,
            float* __restrict__ gs, float* __restrict__ us)
{
    int z = blockIdx.z;
    mmgemm_body(xn, z ? su : sg, z ? us : gs, nullptr,
                NT, NHID, NHID, NHID, NSI);
}

// ---- fused MoE gate+up grouped GEMM: z = 2*e + which
__global__ __launch_bounds__(256, 2)
void moeup_k(const float* __restrict__ xg,
             const float* __restrict__ eg, const float* __restrict__ eu,
             float* __restrict__ gb, float* __restrict__ ub)
{
    int z = blockIdx.z;
    int e = z >> 1;
    int M = d_cnt[e];
    int off = d_off[e];
    const float* B = (z & 1) ? eu : eg;
    float* C       = (z & 1) ? ub : gb;
    mmgemm_body(xg + (long)off * NHID, B + (long)e * NMI * NHID,
                C + (long)off * NMI, nullptr, M, NHID, NHID, NHID, NMI);
}

// ---- MoE down grouped GEMM
__global__ __launch_bounds__(256, 2)
void moedn_k(const float* __restrict__ gb, const float* __restrict__ ed,
             float* __restrict__ yb)
{
    int e = blockIdx.z;
    int M = d_cnt[e];
    int off = d_off[e];
    mmgemm_body(gb + (long)off * NMI, ed + (long)e * NHID * NMI,
                yb + (long)off * NHID, nullptr, M, NMI, NMI, NMI, NHID);
}

// ---------------------------------------------------------------------------
// Elementwise / reduction kernels
// ---------------------------------------------------------------------------
__global__ void rmsnorm_k(const float* __restrict__ x,
                          const float* __restrict__ w,
                          float* __restrict__ o)
{
    int t = blockIdx.x;
    const float* xr = x + (long)t * NHID;
    __shared__ float red[256];
    float s = 0.f;
    for (int i = threadIdx.x; i < NHID; i += 256) { float v = xr[i]; s += v * v; }
    red[threadIdx.x] = s;
    __syncthreads();
    for (int st = 128; st > 0; st >>= 1) {
        if (threadIdx.x < st) red[threadIdx.x] += red[threadIdx.x + st];
        __syncthreads();
    }
    float scale = rsqrtf(red[0] / (float)NHID + 1e-6f);
    for (int i = threadIdx.x; i < NHID; i += 256)
        o[(long)t * NHID + i] = xr[i] * scale * w[i];
}

// RoPE on q,k + scale q by 1/sqrt(HD); transpose q,k to (B,NH,S,HD) and v to
// (B,NH,HD,S) so the PV GEMM is also A * B^T with contiguous K rows.
__global__ void rope_k(const float* __restrict__ qt, const float* __restrict__ kt,
                       const float* __restrict__ vt,
                       const float* __restrict__ cosp, const float* __restrict__ sinp,
                       float* __restrict__ qr, float* __restrict__ kr,
                       float* __restrict__ vrT)
{
    int t = blockIdx.x;                // token
    int n = blockIdx.y;                // head
    int d = threadIdx.x;               // 0..63
    int b = t / NS, s = t % NS;
    long src = (long)t * NHID + n * DHEAD;
    long dst = ((long)(b * NHEAD + n) * NS + s) * DHEAD;
    long bhv = (long)(b * NHEAD + n) * DHEAD * NS;
    float c  = cosp[s * DHEAD + d];
    float sn = sinp[s * DHEAD + d];
    const float inv = 0.08838834764831845f;  // 1/sqrt(128)

    float q0 = qt[src + d], q1 = qt[src + d + 64];
    qr[dst + d]      = (q0 * c - q1 * sn) * inv;
    qr[dst + d + 64] = (q1 * c + q0 * sn) * inv;

    float k0 = kt[src + d], k1 = kt[src + d + 64];
    kr[dst + d]      = k0 * c - k1 * sn;
    kr[dst + d + 64] = k1 * c + k0 * sn;

    vrT[bhv + (long)d * NS + s]        = vt[src + d];
    vrT[bhv + (long)(d + 64) * NS + s] = vt[src + d + 64];
}

__global__ void softmax_causal_k(float* __restrict__ sc)
{
    int q  = blockIdx.x;
    int bh = blockIdx.y;
    float* row = sc + (long)bh * NS * NS + (long)q * NS;
    int len = q + 1;
    __shared__ float red[256];
    int tid = threadIdx.x;

    float m = -1e30f;
    for (int i = tid; i < len; i += 256) m = fmaxf(m, row[i]);
    red[tid] = m;
    __syncthreads();
    for (int st = 128; st > 0; st >>= 1) {
        if (tid < st) red[tid] = fmaxf(red[tid], red[tid + st]);
        __syncthreads();
    }
    m = red[0];
    __syncthreads();

    float s = 0.f;
    for (int i = tid; i < len; i += 256) {
        float e = expf(row[i] - m);
        row[i] = e;
        s += e;
    }
    red[tid] = s;
    __syncthreads();
    for (int st = 128; st > 0; st >>= 1) {
        if (tid < st) red[tid] += red[tid + st];
        __syncthreads();
    }
    float invs = 1.f / red[0];
    for (int i = tid; i < NS; i += 256) {
        if (i < len) row[i] *= invs;
        else         row[i] = 0.f;
    }
}

__global__ void zero_cnt_k() { if (threadIdx.x < NEXP) d_cnt[threadIdx.x] = 0; }

__global__ void gate_k(const float* __restrict__ xn, const float* __restrict__ gw)
{
    int t = blockIdx.x;
    int tid = threadIdx.x, w = tid >> 5, lane = tid & 31;
    const float* xr = xn + (long)t * NHID;
    const float* gr = gw + (long)w * NHID;
    float s = 0.f;
    for (int i = lane; i < NHID; i += 32) s += xr[i] * gr[i];
    for (int o = 16; o; o >>= 1) s += __shfl_xor_sync(0xffffffffu, s, o);
    __shared__ float lg[NEXP];
    if (lane == 0) lg[w] = s;
    __syncthreads();
    if (tid == 0) {
        float mx = lg[0];
        for (int e = 1; e < NEXP; ++e) mx = fmaxf(mx, lg[e]);
        float p[NEXP];
        for (int e = 0; e < NEXP; ++e) p[e] = expf(lg[e] - mx);
        int e0 = 0; float b0 = p[0];
        for (int e = 1; e < NEXP; ++e) if (p[e] > b0) { b0 = p[e]; e0 = e; }
        int e1 = -1; float b1 = -1.f;
        for (int e = 0; e < NEXP; ++e)
            if (e != e0 && p[e] > b1) { b1 = p[e]; e1 = e; }
        float denom = b0 + b1;
        d_e0[t] = e0; d_e1[t] = e1;
        d_w0[t] = b0 / denom; d_w1[t] = b1 / denom;
        d_r0[t] = atomicAdd(&d_cnt[e0], 1);
        d_r1[t] = atomicAdd(&d_cnt[e1], 1);
    }
}

__global__ void scan_k()
{
    if (threadIdx.x == 0) {
        int a = 0;
        for (int e = 0; e < NEXP; ++e) { d_off[e] = a; a += d_cnt[e]; }
    }
}

__global__ void gather_k(const float* __restrict__ xn)
{
    int t = blockIdx.x;
    __shared__ int ss[2];
    if (threadIdx.x == 0) {
        int s0 = d_off[d_e0[t]] + d_r0[t];
        int s1 = d_off[d_e1[t]] + d_r1[t];
        d_s0[t] = s0; d_s1[t] = s1;
        ss[0] = s0; ss[1] = s1;
    }
    __syncthreads();
    const float4* src = (const float4*)(xn + (long)t * NHID);
    float4* dst0 = (float4*)(d_xg + (long)ss[0] * NHID);
    float4* dst1 = (float4*)(d_xg + (long)ss[1] * NHID);
    for (int i = threadIdx.x; i < NHID / 4; i += 256) {
        float4 v = src[i];
        dst0[i] = v;
        dst1[i] = v;
    }
}

__global__ void silumul_k(float* __restrict__ g, const float* __restrict__ u, long n)
{
    long i = (long)blockIdx.x * 256 + threadIdx.x;
    if (i < n) {
        float gv = g[i];
        float s = 1.f / (1.f + expf(-gv));
        g[i] = gv * s * u[i];
    }
}

__global__ void combine_k(const float* __restrict__ x1,
                          const float* __restrict__ sh,
                          float* __restrict__ out)
{
    int t = blockIdx.x;
    float w0 = d_w0[t], w1 = d_w1[t];
    long o0 = (long)d_s0[t] * NHID;
    long o1 = (long)d_s1[t] * NHID;
    for (int i = threadIdx.x; i < NHID; i += 256) {
        long idx = (long)t * NHID + i;
        out[idx] = x1[idx] + sh[idx] + w0 * d_ybuf[o0 + i] + w1 * d_ybuf[o1 + i];
    }
}

// ---------------------------------------------------------------------------
// Launch
// ---------------------------------------------------------------------------
extern "C" void kernel_launch(void* const* d_in, const int* in_sizes, int n_in,
                              void* d_out, int out_size)
{
    (void)in_sizes; (void)n_in; (void)out_size;

    const float* hs   = (const float*)d_in[0];
    const float* ln1  = (const float*)d_in[1];
    const float* ln2  = (const float*)d_in[2];
    const float* q_w  = (const float*)d_in[3];
    const float* k_w  = (const float*)d_in[4];
    const float* v_w  = (const float*)d_in[5];
    const float* o_w  = (const float*)d_in[6];
    const float* cosp = (const float*)d_in[7];
    const float* sinp = (const float*)d_in[8];
    const float* gate = (const float*)d_in[9];
    const float* eg   = (const float*)d_in[10];
    const float* eu   = (const float*)d_in[11];
    const float* ed   = (const float*)d_in[12];
    const float* sg   = (const float*)d_in[13];
    const float* su   = (const float*)d_in[14];
    const float* sd   = (const float*)d_in[15];
    float* out = (float*)d_out;

    float *xn, *qt, *kt, *vt, *qr, *kr, *vrT, *sc, *ctx, *x1;
    float *xg, *gb, *ub, *yb, *gs, *us, *sh;
    cudaGetSymbolAddress((void**)&xn,  d_xn);
    cudaGetSymbolAddress((void**)&qt,  d_qt);
    cudaGetSymbolAddress((void**)&kt,  d_kt);
    cudaGetSymbolAddress((void**)&vt,  d_vt);
    cudaGetSymbolAddress((void**)&qr,  d_qr);
    cudaGetSymbolAddress((void**)&kr,  d_kr);
    cudaGetSymbolAddress((void**)&vrT, d_vrT);
    cudaGetSymbolAddress((void**)&sc,  d_scores);
    cudaGetSymbolAddress((void**)&ctx, d_ctx);
    cudaGetSymbolAddress((void**)&x1,  d_x1);
    cudaGetSymbolAddress((void**)&xg,  d_xg);
    cudaGetSymbolAddress((void**)&gb,  d_gbuf);
    cudaGetSymbolAddress((void**)&ub,  d_ubuf);
    cudaGetSymbolAddress((void**)&yb,  d_ybuf);
    cudaGetSymbolAddress((void**)&gs,  d_gs);
    cudaGetSymbolAddress((void**)&us,  d_us);
    cudaGetSymbolAddress((void**)&sh,  d_sh);

    // raise dynamic smem limits (host-side attribute, executes immediately;
    // idempotent, not a stream op, graph-capture safe)
    cudaFuncSetAttribute(sgemm_bat<false>,
        cudaFuncAttributeMaxDynamicSharedMemorySize, SMEM_BYTES);
    cudaFuncSetAttribute(sgemm_bat<true>,
        cudaFuncAttributeMaxDynamicSharedMemorySize, SMEM_BYTES);
    cudaFuncSetAttribute(qkv_k,
        cudaFuncAttributeMaxDynamicSharedMemorySize, SMEM_BYTES);
    cudaFuncSetAttribute(shup_k,
        cudaFuncAttributeMaxDynamicSharedMemorySize, SMEM_BYTES);
    cudaFuncSetAttribute(moeup_k,
        cudaFuncAttributeMaxDynamicSharedMemorySize, SMEM_BYTES);
    cudaFuncSetAttribute(moedn_k,
        cudaFuncAttributeMaxDynamicSharedMemorySize, SMEM_BYTES);

    const dim3 gQKV(NHID / BN, NT / BM, 3);          // (8, 16, 3)
    const dim3 gScore(NS / BN, NS / BM, NB * NHEAD); // (8, 8, 16)
    const dim3 gPV(DHEAD / BN, NS / BM, NB * NHEAD); // (1, 8, 16)
    const dim3 gProj(NHID / BN, NT / BM);            // (8, 16)
    const dim3 gShUp(NSI / BN, NT / BM, 2);          // (16, 16, 2)
    const dim3 gMoeUp(NMI / BN, NSLOT / BM, 2 * NEXP);
    const dim3 gMoeDn(NHID / BN, NSLOT / BM, NEXP);

    // ---- attention ----
    rmsnorm_k<<<NT, 256>>>(hs, ln1, xn);
    qkv_k<<<gQKV, 256, SMEM_BYTES>>>(xn, q_w, k_w, v_w, qt, kt, vt);
    rope_k<<<dim3(NT, NHEAD), 64>>>(qt, kt, vt, cosp, sinp, qr, kr, vrT);

    sgemm_bat<true><<<gScore, 256, SMEM_BYTES>>>(qr, kr, sc, nullptr,
        NS, DHEAD, DHEAD, DHEAD, NS,
        (long)NS * DHEAD, (long)NS * DHEAD,
        8L * NS * NS, (long)NS * NS);
    softmax_causal_k<<<dim3(NS, NB * NHEAD), 256>>>(sc);
    sgemm_bat<false><<<gPV, 256, SMEM_BYTES>>>(sc, vrT, ctx, nullptr,
        NS, NS, NS, NS, NHID,
        (long)NS * NS, (long)DHEAD * NS,
        (long)NS * NHID, (long)DHEAD);
    sgemm_bat<false><<<gProj, 256, SMEM_BYTES>>>(ctx, o_w, x1, hs,
        NT, NHID, NHID, NHID, NHID, 0, 0, 0, 0);

    // ---- MoE ----
    rmsnorm_k<<<NT, 256>>>(x1, ln2, xn);
    zero_cnt_k<<<1, 32>>>();
    gate_k<<<NT, 256>>>(xn, gate);
    scan_k<<<1, 1>>>();
    gather_k<<<NT, 256>>>(xn);

    moeup_k<<<gMoeUp, 256, SMEM_BYTES>>>(xg, eg, eu, gb, ub);
    silumul_k<<<(unsigned)(((long)NSLOT * NMI + 255) / 256), 256>>>(
        gb, ub, (long)NSLOT * NMI);
    moedn_k<<<gMoeDn, 256, SMEM_BYTES>>>(gb, ed, yb);

    // ---- shared MLP ----
    shup_k<<<gShUp, 256, SMEM_BYTES>>>(xn, sg, su, gs, us);
    silumul_k<<<(unsigned)(((long)NT * NSI + 255) / 256), 256>>>(
        gs, us, (long)NT * NSI);
    sgemm_bat<false><<<gProj, 256, SMEM_BYTES>>>(gs, sd, sh, nullptr,
        NT, NSI, NSI, NSI, NHID, 0, 0, 0, 0);

    // ---- combine ----
    combine_k<<<NT, 256>>>(x1, sh, out);
}

// round 5
// speedup vs baseline: 1.0623x; 1.0623x over previous
#include <cuda_runtime.h>
#include <math.h>

// ---------------------------------------------------------------------------
// Problem constants
// ---------------------------------------------------------------------------
namespace {
constexpr int NB = 2, NS = 1024, NHID = 1024, NHEAD = 8, DHEAD = 128;
constexpr int NEXP = 8, NMI = 1024, NSI = 2048;
constexpr int NT = NB * NS;          // 2048 tokens
constexpr int NSLOT = 2 * NT;        // 4096 expert slots (top-2)

constexpr int BM = 128, BN = 128, BK = 16, PADK = BK + 4;
constexpr int STAGES = 4;
constexpr int SMEM_WORDS_HALF = STAGES * BM * PADK;            // per A or B
constexpr int SMEM_BYTES = 2 * SMEM_WORDS_HALF * (int)sizeof(float);  // 81920
constexpr int PVSPLIT = 4;
constexpr int PVK = NS / PVSPLIT;    // 256
}

// ---------------------------------------------------------------------------
// Static device scratch (no allocations allowed)
// ---------------------------------------------------------------------------
__device__ float d_xn[NT * NHID];
__device__ float d_qt[NT * NHID];
__device__ float d_kt[NT * NHID];
__device__ float d_vt[NT * NHID];
__device__ float d_qr[NT * NHID];     // (B,NH,S,HD) rope'd + scaled, tf32-rounded
__device__ float d_kr[NT * NHID];     // (B,NH,S,HD) tf32-rounded
__device__ float d_vrT[NT * NHID];    // (B,NH,HD,S) tf32-rounded
__device__ float d_scores[(long)NB * NHEAD * NS * NS];   // 64 MB
__device__ float d_ctx[NT * NHID];
__device__ float d_pvp[(long)PVSPLIT * NT * NHID];       // PV split-K partials
__device__ float d_x1[NT * NHID];
__device__ float d_xg[NSLOT * NHID];
__device__ float d_gbuf[NSLOT * NMI];
__device__ float d_ubuf[NSLOT * NMI];
__device__ float d_ybuf[NSLOT * NHID];
__device__ float d_gs[NT * NSI];
__device__ float d_us[NT * NSI];
__device__ float d_sh[NT * NHID];
__device__ int   d_cnt[NEXP];
__device__ int   d_off[NEXP];
__device__ int   d_e0[NT], d_e1[NT], d_r0[NT], d_r1[NT], d_s0[NT], d_s1[NT];
__device__ float d_w0[NT], d_w1[NT];

// ---------------------------------------------------------------------------
// helpers
// ---------------------------------------------------------------------------
__device__ __forceinline__ unsigned smem_u32(const void* p) {
    return (unsigned)__cvta_generic_to_shared(p);
}

__device__ __forceinline__ void cp16(unsigned dst, const void* src, bool pred) {
    int sz = pred ? 16 : 0;
    asm volatile("cp.async.cg.shared.global [%0], [%1], 16, %2;\n"
                 :: "r"(dst), "l"(src), "r"(sz));
}

// RNA-round an fp32 value to tf32 precision (result stays an fp32 value)
__device__ __forceinline__ float rna(float x) {
    unsigned u;
    asm("cvt.rna.tf32.f32 %0, %1;" : "=r"(u) : "f"(x));
    return __uint_as_float(u);
}

__device__ __forceinline__ void mma_tf32(float c[4],
    unsigned a0, unsigned a1, unsigned a2, unsigned a3,
    unsigned b0, unsigned b1)
{
    asm volatile(
        "mma.sync.aligned.m16n8k8.row.col.f32.tf32.tf32.f32 "
        "{%0,%1,%2,%3}, {%4,%5,%6,%7}, {%8,%9}, {%0,%1,%2,%3};\n"
        : "+f"(c[0]), "+f"(c[1]), "+f"(c[2]), "+f"(c[3])
        : "r"(a0), "r"(a1), "r"(a2), "r"(a3), "r"(b0), "r"(b1));
}

// ---------------------------------------------------------------------------
// TF32 tensor-core GEMM:  C[M,N] = A[M,K] * B^T  with B stored (N,K) row-major
// 128x128x16 block tile, 256 threads = 8 warps, each warp 64x32 (4x4 mma m16n8k8)
// 4-stage cp.async pipeline, ONE __syncthreads per k-iter, dynamic smem.
// Operands are fed to mma as raw fp32 bits (HW truncates to tf32; producers
// already RNA-round activations). M may be ragged (zfill + store guards).
// ---------------------------------------------------------------------------
__device__ __forceinline__ void mmgemm_body(
    const float* __restrict__ A, const float* __restrict__ Bm,
    float* __restrict__ C, const float* __restrict__ resid,
    int M, int K, int lda, int ldb, int ldc)
{
    extern __shared__ float sm[];
    float (*As)[BM][PADK] = reinterpret_cast<float (*)[BM][PADK]>(sm);
    float (*Bs)[BM][PADK] =
        reinterpret_cast<float (*)[BM][PADK]>(sm + SMEM_WORDS_HALF);

    const int tid  = threadIdx.x;
    const int wid  = tid >> 5;
    const int lane = tid & 31;
    const int g    = lane >> 2;          // 0..7
    const int tg   = lane & 3;           // 0..3
    const int wm   = (wid & 1) * 64;     // warp m-offset
    const int wn   = (wid >> 1) * 32;    // warp n-offset
    const int row0 = blockIdx.y * BM;
    const int col0 = blockIdx.x * BN;
    if (row0 >= M) return;

    float c[4][4][4];
#pragma unroll
    for (int mi = 0; mi < 4; ++mi)
#pragma unroll
        for (int ni = 0; ni < 4; ++ni)
#pragma unroll
            for (int r = 0; r < 4; ++r) c[mi][ni][r] = 0.f;

    const int lr = tid >> 2;             // 0..63
    const int lq = (tid & 3) * 4;        // 0,4,8,12
    const int niter = K / BK;

    // ---- prologue: stages 0..2 ----
#pragma unroll
    for (int st = 0; st < STAGES - 1; ++st) {
        if (st < niter) {
            const int k0 = st * BK;
#pragma unroll
            for (int h = 0; h < 2; ++h) {
                int r = lr + h * 64;
                cp16(smem_u32(&As[st][r][lq]),
                     A + (long)(row0 + r) * lda + k0 + lq, (row0 + r) < M);
            }
#pragma unroll
            for (int h = 0; h < 2; ++h) {
                int r = lr + h * 64;
                cp16(smem_u32(&Bs[st][r][lq]),
                     Bm + (long)(col0 + r) * ldb + k0 + lq, true);
            }
        }
        asm volatile("cp.async.commit_group;\n");
    }

    int s = 0;
    for (int it = 0; it < niter; ++it) {
        asm volatile("cp.async.wait_group 2;\n");
        __syncthreads();

        const int pf = it + STAGES - 1;
        if (pf < niter) {
            int sl = s + STAGES - 1; if (sl >= STAGES) sl -= STAGES;
            const int k0 = pf * BK;
#pragma unroll
            for (int h = 0; h < 2; ++h) {
                int r = lr + h * 64;
                cp16(smem_u32(&As[sl][r][lq]),
                     A + (long)(row0 + r) * lda + k0 + lq, (row0 + r) < M);
            }
#pragma unroll
            for (int h = 0; h < 2; ++h) {
                int r = lr + h * 64;
                cp16(smem_u32(&Bs[sl][r][lq]),
                     Bm + (long)(col0 + r) * ldb + k0 + lq, true);
            }
        }
        asm volatile("cp.async.commit_group;\n");

#pragma unroll
        for (int kk = 0; kk < 2; ++kk) {
            const int kb = kk * 8;
            unsigned af[4][4], bf[4][2];
#pragma unroll
            for (int mi = 0; mi < 4; ++mi) {
                int mrow = wm + mi * 16;
                af[mi][0] = __float_as_uint(As[s][mrow + g    ][kb + tg    ]);
                af[mi][1] = __float_as_uint(As[s][mrow + g + 8][kb + tg    ]);
                af[mi][2] = __float_as_uint(As[s][mrow + g    ][kb + tg + 4]);
                af[mi][3] = __float_as_uint(As[s][mrow + g + 8][kb + tg + 4]);
            }
#pragma unroll
            for (int ni = 0; ni < 4; ++ni) {
                int nrow = wn + ni * 8;
                bf[ni][0] = __float_as_uint(Bs[s][nrow + g][kb + tg    ]);
                bf[ni][1] = __float_as_uint(Bs[s][nrow + g][kb + tg + 4]);
            }
#pragma unroll
            for (int mi = 0; mi < 4; ++mi)
#pragma unroll
                for (int ni = 0; ni < 4; ++ni)
                    mma_tf32(c[mi][ni], af[mi][0], af[mi][1], af[mi][2], af[mi][3],
                             bf[ni][0], bf[ni][1]);
        }
        if (++s >= STAGES) s = 0;
    }

    // ---- epilogue ----
#pragma unroll
    for (int mi = 0; mi < 4; ++mi) {
#pragma unroll
        for (int half = 0; half < 2; ++half) {
            int r = row0 + wm + mi * 16 + g + half * 8;
            if (r < M) {
#pragma unroll
                for (int ni = 0; ni < 4; ++ni) {
                    long off = (long)r * ldc + col0 + wn + ni * 8 + tg * 2;
                    float2 v;
                    v.x = c[mi][ni][half * 2 + 0];
                    v.y = c[mi][ni][half * 2 + 1];
                    if (resid) {
                        float2 rr = *(const float2*)(resid + off);
                        v.x += rr.x; v.y += rr.y;
                    }
                    *(float2*)(C + off) = v;
                }
            }
        }
    }
}

// ---- generic batched (A * B^T); used for scores (causal), O-proj, shared-down
template <bool CAUSAL>
__global__ __launch_bounds__(256, 2)
void sgemm_bat(
    const float* __restrict__ A, const float* __restrict__ Bm,
    float* __restrict__ C, const float* __restrict__ resid,
    int M, int K, int lda, int ldb, int ldc,
    long sA, long sB, long sC_hi, long sC_lo)
{
    int z = blockIdx.z;
    if (CAUSAL) {
        if (blockIdx.x > blockIdx.y) return;   // tiles strictly above diagonal
    }
    mmgemm_body(A + (long)z * sA, Bm + (long)z * sB,
                C + (long)(z >> 3) * sC_hi + (long)(z & 7) * sC_lo,
                resid, M, K, lda, ldb, ldc);
}

// ---- fused Q/K/V projection: z selects the weight + destination
__global__ __launch_bounds__(256, 2)
void qkv_k(const float* __restrict__ xn,
           const float* __restrict__ qw, const float* __restrict__ kw,
           const float* __restrict__ vw,
           float* __restrict__ qt, float* __restrict__ kt, float* __restrict__ vt)
{
    int z = blockIdx.z;
    const float* B = (z == 0) ? qw : (z == 1) ? kw : vw;
    float* C       = (z == 0) ? qt : (z == 1) ? kt : vt;
    mmgemm_body(xn, B, C, nullptr, NT, NHID, NHID, NHID, NHID);
}

// ---- PV with split-K: z = head*PVSPLIT + chunk; writes partial planes
__global__ __launch_bounds__(256, 2)
void pv_k(const float* __restrict__ sc, const float* __restrict__ vrT,
          float* __restrict__ pvp)
{
    int z = blockIdx.z;
    int head = z >> 2, chunk = z & 3;
    mmgemm_body(sc  + (long)head * NS * NS    + chunk * PVK,
                vrT + (long)head * DHEAD * NS + chunk * PVK,
                pvp + (long)chunk * NT * NHID
                    + (long)(head >> 3) * NS * NHID + (head & 7) * DHEAD,
                nullptr, NS, PVK, NS, NS, NHID);
}

// ---- reduce PV partials into ctx (tf32-rounded; feeds O-proj)
__global__ void pvred_k(const float* __restrict__ pvp, float* __restrict__ ctx)
{
    long i = (long)blockIdx.x * 256 + threadIdx.x;
    const long P = (long)NT * NHID;
    float v = pvp[i] + pvp[i + P] + pvp[i + 2 * P] + pvp[i + 3 * P];
    ctx[i] = rna(v);
}

// ---- fused shared-MLP gate+up: z selects sg->gs / su->us
__global__ __launch_bounds__(256, 2)
void shup_k(const float* __restrict__ xn,
            const float* __restrict__ sg, const float* __restrict__ su,
            float* __restrict__ gs, float* __restrict__ us)
{
    int z = blockIdx.z;
    mmgemm_body(xn, z ? su : sg, z ? us : gs, nullptr,
                NT, NHID, NHID, NHID, NSI);
}

// ---- fused MoE gate+up grouped GEMM: z = 2*e + which
__global__ __launch_bounds__(256, 2)
void moeup_k(const float* __restrict__ xg,
             const float* __restrict__ eg, const float* __restrict__ eu,
             float* __restrict__ gb, float* __restrict__ ub)
{
    int z = blockIdx.z;
    int e = z >> 1;
    int M = d_cnt[e];
    int off = d_off[e];
    const float* B = (z & 1) ? eu : eg;
    float* C       = (z & 1) ? ub : gb;
    mmgemm_body(xg + (long)off * NHID, B + (long)e * NMI * NHID,
                C + (long)off * NMI, nullptr, M, NHID, NHID, NHID, NMI);
}

// ---- MoE down grouped GEMM
__global__ __launch_bounds__(256, 2)
void moedn_k(const float* __restrict__ gb, const float* __restrict__ ed,
             float* __restrict__ yb)
{
    int e = blockIdx.z;
    int M = d_cnt[e];
    int off = d_off[e];
    mmgemm_body(gb + (long)off * NMI, ed + (long)e * NHID * NMI,
                yb + (long)off * NHID, nullptr, M, NMI, NMI, NMI, NHID);
}

// ---------------------------------------------------------------------------
// Elementwise / reduction kernels  (GEMM-feeding outputs are tf32 RNA-rounded)
// ---------------------------------------------------------------------------
__global__ void rmsnorm_k(const float* __restrict__ x,
                          const float* __restrict__ w,
                          float* __restrict__ o)
{
    int t = blockIdx.x;
    const float* xr = x + (long)t * NHID;
    __shared__ float red[256];
    float s = 0.f;
    for (int i = threadIdx.x; i < NHID; i += 256) { float v = xr[i]; s += v * v; }
    red[threadIdx.x] = s;
    __syncthreads();
    for (int st = 128; st > 0; st >>= 1) {
        if (threadIdx.x < st) red[threadIdx.x] += red[threadIdx.x + st];
        __syncthreads();
    }
    float scale = rsqrtf(red[0] / (float)NHID + 1e-6f);
    for (int i = threadIdx.x; i < NHID; i += 256)
        o[(long)t * NHID + i] = rna(xr[i] * scale * w[i]);
}

// RoPE on q,k + scale q by 1/sqrt(HD); transpose q,k to (B,NH,S,HD) and v to
// (B,NH,HD,S) so the PV GEMM is also A * B^T with contiguous K rows.
__global__ void rope_k(const float* __restrict__ qt, const float* __restrict__ kt,
                       const float* __restrict__ vt,
                       const float* __restrict__ cosp, const float* __restrict__ sinp,
                       float* __restrict__ qr, float* __restrict__ kr,
                       float* __restrict__ vrT)
{
    int t = blockIdx.x;                // token
    int n = blockIdx.y;                // head
    int d = threadIdx.x;               // 0..63
    int b = t / NS, s = t % NS;
    long src = (long)t * NHID + n * DHEAD;
    long dst = ((long)(b * NHEAD + n) * NS + s) * DHEAD;
    long bhv = (long)(b * NHEAD + n) * DHEAD * NS;
    float c  = cosp[s * DHEAD + d];
    float sn = sinp[s * DHEAD + d];
    const float inv = 0.08838834764831845f;  // 1/sqrt(128)

    float q0 = qt[src + d], q1 = qt[src + d + 64];
    qr[dst + d]      = rna((q0 * c - q1 * sn) * inv);
    qr[dst + d + 64] = rna((q1 * c + q0 * sn) * inv);

    float k0 = kt[src + d], k1 = kt[src + d + 64];
    kr[dst + d]      = rna(k0 * c - k1 * sn);
    kr[dst + d + 64] = rna(k1 * c + k0 * sn);

    vrT[bhv + (long)d * NS + s]        = rna(vt[src + d]);
    vrT[bhv + (long)(d + 64) * NS + s] = rna(vt[src + d + 64]);
}

__global__ void softmax_causal_k(float* __restrict__ sc)
{
    int q  = blockIdx.x;
    int bh = blockIdx.y;
    float* row = sc + (long)bh * NS * NS + (long)q * NS;
    int len = q + 1;
    __shared__ float red[256];
    int tid = threadIdx.x;

    float m = -1e30f;
    for (int i = tid; i < len; i += 256) m = fmaxf(m, row[i]);
    red[tid] = m;
    __syncthreads();
    for (int st = 128; st > 0; st >>= 1) {
        if (tid < st) red[tid] = fmaxf(red[tid], red[tid + st]);
        __syncthreads();
    }
    m = red[0];
    __syncthreads();

    float s = 0.f;
    for (int i = tid; i < len; i += 256) {
        float e = expf(row[i] - m);
        row[i] = e;
        s += e;
    }
    red[tid] = s;
    __syncthreads();
    for (int st = 128; st > 0; st >>= 1) {
        if (tid < st) red[tid] += red[tid + st];
        __syncthreads();
    }
    float invs = 1.f / red[0];
    for (int i = tid; i < NS; i += 256) {
        if (i < len) row[i] = rna(row[i] * invs);
        else         row[i] = 0.f;
    }
}

__global__ void zero_cnt_k() { if (threadIdx.x < NEXP) d_cnt[threadIdx.x] = 0; }

__global__ void gate_k(const float* __restrict__ xn, const float* __restrict__ gw)
{
    int t = blockIdx.x;
    int tid = threadIdx.x, w = tid >> 5, lane = tid & 31;
    const float* xr = xn + (long)t * NHID;
    const float* gr = gw + (long)w * NHID;
    float s = 0.f;
    for (int i = lane; i < NHID; i += 32) s += xr[i] * gr[i];
    for (int o = 16; o; o >>= 1) s += __shfl_xor_sync(0xffffffffu, s, o);
    __shared__ float lg[NEXP];
    if (lane == 0) lg[w] = s;
    __syncthreads();
    if (tid == 0) {
        float mx = lg[0];
        for (int e = 1; e < NEXP; ++e) mx = fmaxf(mx, lg[e]);
        float p[NEXP];
        for (int e = 0; e < NEXP; ++e) p[e] = expf(lg[e] - mx);
        int e0 = 0; float b0 = p[0];
        for (int e = 1; e < NEXP; ++e) if (p[e] > b0) { b0 = p[e]; e0 = e; }
        int e1 = -1; float b1 = -1.f;
        for (int e = 0; e < NEXP; ++e)
            if (e != e0 && p[e] > b1) { b1 = p[e]; e1 = e; }
        float denom = b0 + b1;
        d_e0[t] = e0; d_e1[t] = e1;
        d_w0[t] = b0 / denom; d_w1[t] = b1 / denom;
        d_r0[t] = atomicAdd(&d_cnt[e0], 1);
        d_r1[t] = atomicAdd(&d_cnt[e1], 1);
    }
}

__global__ void scan_k()
{
    if (threadIdx.x == 0) {
        int a = 0;
        for (int e = 0; e < NEXP; ++e) { d_off[e] = a; a += d_cnt[e]; }
    }
}

__global__ void gather_k(const float* __restrict__ xn)
{
    int t = blockIdx.x;
    __shared__ int ss[2];
    if (threadIdx.x == 0) {
        int s0 = d_off[d_e0[t]] + d_r0[t];
        int s1 = d_off[d_e1[t]] + d_r1[t];
        d_s0[t] = s0; d_s1[t] = s1;
        ss[0] = s0; ss[1] = s1;
    }
    __syncthreads();
    const float4* src = (const float4*)(xn + (long)t * NHID);
    float4* dst0 = (float4*)(d_xg + (long)ss[0] * NHID);
    float4* dst1 = (float4*)(d_xg + (long)ss[1] * NHID);
    for (int i = threadIdx.x; i < NHID / 4; i += 256) {
        float4 v = src[i];
        dst0[i] = v;
        dst1[i] = v;
    }
}

__global__ void silumul_k(float* __restrict__ g, const float* __restrict__ u, long n)
{
    long i = (long)blockIdx.x * 256 + threadIdx.x;
    if (i < n) {
        float gv = g[i];
        float s = 1.f / (1.f + expf(-gv));
        g[i] = rna(gv * s * u[i]);
    }
}

__global__ void combine_k(const float* __restrict__ x1,
                          const float* __restrict__ sh,
                          float* __restrict__ out)
{
    int t = blockIdx.x;
    float w0 = d_w0[t], w1 = d_w1[t];
    long o0 = (long)d_s0[t] * NHID;
    long o1 = (long)d_s1[t] * NHID;
    for (int i = threadIdx.x; i < NHID; i += 256) {
        long idx = (long)t * NHID + i;
        out[idx] = x1[idx] + sh[idx] + w0 * d_ybuf[o0 + i] + w1 * d_ybuf[o1 + i];
    }
}

// ---------------------------------------------------------------------------
// Launch
// ---------------------------------------------------------------------------
extern "C" void kernel_launch(void* const* d_in, const int* in_sizes, int n_in,
                              void* d_out, int out_size)
{
    (void)in_sizes; (void)n_in; (void)out_size;

    const float* hs   = (const float*)d_in[0];
    const float* ln1  = (const float*)d_in[1];
    const float* ln2  = (const float*)d_in[2];
    const float* q_w  = (const float*)d_in[3];
    const float* k_w  = (const float*)d_in[4];
    const float* v_w  = (const float*)d_in[5];
    const float* o_w  = (const float*)d_in[6];
    const float* cosp = (const float*)d_in[7];
    const float* sinp = (const float*)d_in[8];
    const float* gate = (const float*)d_in[9];
    const float* eg   = (const float*)d_in[10];
    const float* eu   = (const float*)d_in[11];
    const float* ed   = (const float*)d_in[12];
    const float* sg   = (const float*)d_in[13];
    const float* su   = (const float*)d_in[14];
    const float* sd   = (const float*)d_in[15];
    float* out = (float*)d_out;

    float *xn, *qt, *kt, *vt, *qr, *kr, *vrT, *sc, *ctx, *pvp, *x1;
    float *xg, *gb, *ub, *yb, *gs, *us, *sh;
    cudaGetSymbolAddress((void**)&xn,  d_xn);
    cudaGetSymbolAddress((void**)&qt,  d_qt);
    cudaGetSymbolAddress((void**)&kt,  d_kt);
    cudaGetSymbolAddress((void**)&vt,  d_vt);
    cudaGetSymbolAddress((void**)&qr,  d_qr);
    cudaGetSymbolAddress((void**)&kr,  d_kr);
    cudaGetSymbolAddress((void**)&vrT, d_vrT);
    cudaGetSymbolAddress((void**)&sc,  d_scores);
    cudaGetSymbolAddress((void**)&ctx, d_ctx);
    cudaGetSymbolAddress((void**)&pvp, d_pvp);
    cudaGetSymbolAddress((void**)&x1,  d_x1);
    cudaGetSymbolAddress((void**)&xg,  d_xg);
    cudaGetSymbolAddress((void**)&gb,  d_gbuf);
    cudaGetSymbolAddress((void**)&ub,  d_ubuf);
    cudaGetSymbolAddress((void**)&yb,  d_ybuf);
    cudaGetSymbolAddress((void**)&gs,  d_gs);
    cudaGetSymbolAddress((void**)&us,  d_us);
    cudaGetSymbolAddress((void**)&sh,  d_sh);

    // raise dynamic smem limits (host-side attribute, not a stream op)
    cudaFuncSetAttribute(sgemm_bat<false>,
        cudaFuncAttributeMaxDynamicSharedMemorySize, SMEM_BYTES);
    cudaFuncSetAttribute(sgemm_bat<true>,
        cudaFuncAttributeMaxDynamicSharedMemorySize, SMEM_BYTES);
    cudaFuncSetAttribute(qkv_k,
        cudaFuncAttributeMaxDynamicSharedMemorySize, SMEM_BYTES);
    cudaFuncSetAttribute(pv_k,
        cudaFuncAttributeMaxDynamicSharedMemorySize, SMEM_BYTES);
    cudaFuncSetAttribute(shup_k,
        cudaFuncAttributeMaxDynamicSharedMemorySize, SMEM_BYTES);
    cudaFuncSetAttribute(moeup_k,
        cudaFuncAttributeMaxDynamicSharedMemorySize, SMEM_BYTES);
    cudaFuncSetAttribute(moedn_k,
        cudaFuncAttributeMaxDynamicSharedMemorySize, SMEM_BYTES);

    const dim3 gQKV(NHID / BN, NT / BM, 3);          // (8, 16, 3)
    const dim3 gScore(NS / BN, NS / BM, NB * NHEAD); // (8, 8, 16)
    const dim3 gPV(DHEAD / BN, NS / BM, NB * NHEAD * PVSPLIT); // (1, 8, 64)
    const dim3 gProj(NHID / BN, NT / BM);            // (8, 16)
    const dim3 gShUp(NSI / BN, NT / BM, 2);          // (16, 16, 2)
    const dim3 gMoeUp(NMI / BN, NSLOT / BM, 2 * NEXP);
    const dim3 gMoeDn(NHID / BN, NSLOT / BM, NEXP);

    // ---- attention ----
    rmsnorm_k<<<NT, 256>>>(hs, ln1, xn);
    qkv_k<<<gQKV, 256, SMEM_BYTES>>>(xn, q_w, k_w, v_w, qt, kt, vt);
    rope_k<<<dim3(NT, NHEAD), 64>>>(qt, kt, vt, cosp, sinp, qr, kr, vrT);

    sgemm_bat<true><<<gScore, 256, SMEM_BYTES>>>(qr, kr, sc, nullptr,
        NS, DHEAD, DHEAD, DHEAD, NS,
        (long)NS * DHEAD, (long)NS * DHEAD,
        8L * NS * NS, (long)NS * NS);
    softmax_causal_k<<<dim3(NS, NB * NHEAD), 256>>>(sc);
    pv_k<<<gPV, 256, SMEM_BYTES>>>(sc, vrT, pvp);
    pvred_k<<<(unsigned)((long)NT * NHID / 256), 256>>>(pvp, ctx);
    sgemm_bat<false><<<gProj, 256, SMEM_BYTES>>>(ctx, o_w, x1, hs,
        NT, NHID, NHID, NHID, NHID, 0, 0, 0, 0);

    // ---- MoE ----
    rmsnorm_k<<<NT, 256>>>(x1, ln2, xn);
    zero_cnt_k<<<1, 32>>>();
    gate_k<<<NT, 256>>>(xn, gate);
    scan_k<<<1, 1>>>();
    gather_k<<<NT, 256>>>(xn);

    moeup_k<<<gMoeUp, 256, SMEM_BYTES>>>(xg, eg, eu, gb, ub);
    silumul_k<<<(unsigned)(((long)NSLOT * NMI + 255) / 256), 256>>>(
        gb, ub, (long)NSLOT * NMI);
    moedn_k<<<gMoeDn, 256, SMEM_BYTES>>>(gb, ed, yb);

    // ---- shared MLP ----
    shup_k<<<gShUp, 256, SMEM_BYTES>>>(xn, sg, su, gs, us);
    silumul_k<<<(unsigned)(((long)NT * NSI + 255) / 256), 256>>>(
        gs, us, (long)NT * NSI);
    sgemm_bat<false><<<gProj, 256, SMEM_BYTES>>>(gs, sd, sh, nullptr,
        NT, NSI, NSI, NSI, NHID, 0, 0, 0, 0);

    // ---- combine ----
    combine_k<<<NT, 256>>>(x1, sh, out);
}